// round 2
// baseline (speedup 1.0000x reference)
#include <cuda_runtime.h>
#include <math.h>

// Rodrigues: twist [N,3] f32 -> rotmat [N,3,3] f32, N = 4096*2048 = 8388608.
// Memory-bound. Stage via smem so all global traffic is coalesced float4.

static constexpr int ROWS_PER_BLOCK = 256;   // == blockDim.x
static constexpr int IN_FLOATS  = ROWS_PER_BLOCK * 3;   // 768
static constexpr int OUT_FLOATS = ROWS_PER_BLOCK * 9;   // 2304

__global__ __launch_bounds__(ROWS_PER_BLOCK)
void twist2mat_kernel(const float* __restrict__ in, float* __restrict__ out, int n_rows) {
    __shared__ float s_in[IN_FLOATS];
    __shared__ float s_out[OUT_FLOATS];

    const int tid  = threadIdx.x;
    const int base = blockIdx.x * ROWS_PER_BLOCK;   // first row of this block

    // ---- coalesced vectorized input load: 192 float4 per block ----
    {
        const float4* gin4 = reinterpret_cast<const float4*>(in + (size_t)base * 3);
        float4* sin4 = reinterpret_cast<float4*>(s_in);
        #pragma unroll
        for (int i = tid; i < IN_FLOATS / 4; i += ROWS_PER_BLOCK) {
            sin4[i] = gin4[i];
        }
    }
    __syncthreads();

    // ---- per-row Rodrigues ----
    {
        const float x = s_in[tid * 3 + 0];
        const float y = s_in[tid * 3 + 1];
        const float z = s_in[tid * 3 + 2];

        const float r  = fmaxf(sqrtf(x * x + y * y + z * z), 1e-5f);
        const float ir = 1.0f / r;
        const float a0 = x * ir, a1 = y * ir, a2 = z * ir;

        float s, c;
        sincosf(r, &s, &c);             // precise; kernel is HBM-bound so this is free
        const float c1 = 1.0f - c;

        const float a00 = a0 * a0, a11 = a1 * a1, a22 = a2 * a2;
        const float a01 = a0 * a1, a02 = a0 * a2, a12 = a1 * a2;

        float* o = s_out + tid * 9;     // stride 9: bank-conflict-free (gcd(9,32)=1)
        o[0] = fmaf(c1, -(a11 + a22), 1.0f);
        o[1] = fmaf(c1, a01, -a2 * s);
        o[2] = fmaf(c1, a02,  a1 * s);
        o[3] = fmaf(c1, a01,  a2 * s);
        o[4] = fmaf(c1, -(a00 + a22), 1.0f);
        o[5] = fmaf(c1, a12, -a0 * s);
        o[6] = fmaf(c1, a02, -a1 * s);
        o[7] = fmaf(c1, a12,  a0 * s);
        o[8] = fmaf(c1, -(a00 + a11), 1.0f);
    }
    __syncthreads();

    // ---- coalesced vectorized output store: 576 float4 per block ----
    {
        float4* gout4 = reinterpret_cast<float4*>(out + (size_t)base * 9);
        const float4* sout4 = reinterpret_cast<const float4*>(s_out);
        #pragma unroll
        for (int i = tid; i < OUT_FLOATS / 4; i += ROWS_PER_BLOCK) {
            gout4[i] = sout4[i];
        }
    }
}

extern "C" void kernel_launch(void* const* d_in, const int* in_sizes, int n_in,
                              void* d_out, int out_size) {
    const float* in = (const float*)d_in[0];
    float* out = (float*)d_out;
    const int n_rows = in_sizes[0] / 3;           // 8388608
    const int n_blocks = n_rows / ROWS_PER_BLOCK; // 32768 (exact)
    twist2mat_kernel<<<n_blocks, ROWS_PER_BLOCK>>>(in, out, n_rows);
}

// round 6
// speedup vs baseline: 1.0360x; 1.0360x over previous
#include <cuda_runtime.h>
#include <cstdint>
#include <math.h>

// Rodrigues: twist [N,3] f32 -> rotmat [N,3,3] f32, N = 8388608.
// HBM-bound. cp.async double-buffered input, smem-staged coalesced I/O,
// 4 tiles of 512 rows per block to hide load latency and smooth DRAM demand.

static constexpr int THREADS         = 256;
static constexpr int ROWS_PER_TILE   = 512;                       // 2 rows/thread
static constexpr int TILES_PER_BLOCK = 4;
static constexpr int ROWS_PER_BLOCK  = ROWS_PER_TILE * TILES_PER_BLOCK;  // 2048
static constexpr int IN_FLOATS       = ROWS_PER_TILE * 3;         // 1536 (384 float4)
static constexpr int OUT_FLOATS      = ROWS_PER_TILE * 9;         // 4608 (1152 float4)
static constexpr int IN_F4           = IN_FLOATS / 4;             // 384
static constexpr int OUT_F4          = OUT_FLOATS / 4;            // 1152

__device__ __forceinline__ void cp_async16(uint32_t saddr, const float4* gaddr) {
    asm volatile("cp.async.cg.shared.global [%0], [%1], 16;" :: "r"(saddr), "l"(gaddr));
}
__device__ __forceinline__ void cp_commit() {
    asm volatile("cp.async.commit_group;");
}
__device__ __forceinline__ void cp_wait1() {
    asm volatile("cp.async.wait_group 1;");
}

__global__ __launch_bounds__(THREADS)
void twist2mat_kernel(const float* __restrict__ in, float* __restrict__ out) {
    __shared__ float s_in[2][IN_FLOATS];    // 2 x 6 KB
    __shared__ float s_out[OUT_FLOATS];     // 18 KB

    const int tid = threadIdx.x;
    const long long block_row0 = (long long)blockIdx.x * ROWS_PER_BLOCK;
    const float4* gin4 = reinterpret_cast<const float4*>(in) + block_row0 * 3 / 4;
    float4* gout4 = reinterpret_cast<float4*>(out) + block_row0 * 9 / 4;

    const uint32_t s_in_addr0 = (uint32_t)__cvta_generic_to_shared(&s_in[0][0]);
    const uint32_t s_in_addr1 = (uint32_t)__cvta_generic_to_shared(&s_in[1][0]);

    // ---- prefetch tiles 0 and 1 ----
    #pragma unroll
    for (int tt = 0; tt < 2; tt++) {
        const uint32_t sbase = tt ? s_in_addr1 : s_in_addr0;
        const float4* gbase = gin4 + (size_t)tt * IN_F4;
        for (int i = tid; i < IN_F4; i += THREADS)
            cp_async16(sbase + (uint32_t)i * 16u, gbase + i);
        cp_commit();
    }

    for (int t = 0; t < TILES_PER_BLOCK; t++) {
        cp_wait1();              // tile t landed in s_in[t&1]
        __syncthreads();         // tile-t data visible; prev-iter s_out reads all done

        // ---- compute 2 rows/thread: rows tid and 256+tid of this tile ----
        const float* si = s_in[t & 1];
        #pragma unroll
        for (int r = 0; r < 2; r++) {
            const int row = r * THREADS + tid;
            const float x = si[row * 3 + 0];
            const float y = si[row * 3 + 1];
            const float z = si[row * 3 + 2];

            const float rr = fmaxf(sqrtf(x * x + y * y + z * z), 1e-5f);
            const float ir = 1.0f / rr;
            const float a0 = x * ir, a1 = y * ir, a2 = z * ir;

            float s, c;
            sincosf(rr, &s, &c);
            const float c1 = 1.0f - c;

            const float a00 = a0 * a0, a11 = a1 * a1, a22 = a2 * a2;
            const float a01 = a0 * a1, a02 = a0 * a2, a12 = a1 * a2;

            float* o = s_out + row * 9;   // stride 9: conflict-free
            o[0] = fmaf(c1, -(a11 + a22), 1.0f);
            o[1] = fmaf(c1, a01, -a2 * s);
            o[2] = fmaf(c1, a02,  a1 * s);
            o[3] = fmaf(c1, a01,  a2 * s);
            o[4] = fmaf(c1, -(a00 + a22), 1.0f);
            o[5] = fmaf(c1, a12, -a0 * s);
            o[6] = fmaf(c1, a02, -a1 * s);
            o[7] = fmaf(c1, a12,  a0 * s);
            o[8] = fmaf(c1, -(a00 + a11), 1.0f);
        }
        __syncthreads();         // s_out complete; s_in[t&1] fully consumed

        // ---- prefetch tile t+2 into the buffer just freed ----
        if (t + 2 < TILES_PER_BLOCK) {
            const uint32_t sbase = (t & 1) ? s_in_addr1 : s_in_addr0;
            const float4* gbase = gin4 + (size_t)(t + 2) * IN_F4;
            for (int i = tid; i < IN_F4; i += THREADS)
                cp_async16(sbase + (uint32_t)i * 16u, gbase + i);
        }
        cp_commit();             // always commit (empty groups complete immediately)

        // ---- coalesced store of tile t ----
        float4* go = gout4 + (size_t)t * OUT_F4;
        const float4* so4 = reinterpret_cast<const float4*>(s_out);
        for (int i = tid; i < OUT_F4; i += THREADS)
            go[i] = so4[i];
        // next iteration's top __syncthreads guards s_out reuse
    }
}

extern "C" void kernel_launch(void* const* d_in, const int* in_sizes, int n_in,
                              void* d_out, int out_size) {
    const float* in = (const float*)d_in[0];
    float* out = (float*)d_out;
    const int n_rows = in_sizes[0] / 3;                 // 8388608
    const int n_blocks = n_rows / ROWS_PER_BLOCK;       // 4096 (exact)
    twist2mat_kernel<<<n_blocks, THREADS>>>(in, out);
}